// round 17
// baseline (speedup 1.0000x reference)
#include <cuda_runtime.h>
#include <cuda_fp16.h>
#include <math.h>
#include <stdint.h>

#define DIMV 1024
#define HEADS 16
#define DHEAD 64
#define BATCH 16
#define SEQ 512
#define INNERV 1024
#define CPBD 512
#define FFH 2730
#define LDT 2752            /* padded leading dim for t / cWout (halfs): 43*64 */
#define MROWS (BATCH*SEQ)   /* 8192 */
#define EPSV 1e-5f

// ---------------- scratch (static device arrays; no allocations) ----------------
__device__ float  g_bias[HEADS * 1023];
__device__ __half g_xn[(size_t)MROWS * DIMV];
__device__ __half g_qkv[(size_t)3 * MROWS * INNERV];   // q | k | v  ([b,h,n,d] each)
__device__ __half g_o[(size_t)MROWS * INNERV];
__device__ float  g_y[(size_t)MROWS * DIMV];           // fp32 residual copy
__device__ __half g_yh[(size_t)MROWS * DIMV];          // half mirror
__device__ __half g_t[(size_t)MROWS * LDT];            // zero-init; padding never written
// half-preconverted weights ([n][k] layouts)
__device__ __half g_cWqkvT[(size_t)3 * INNERV * DIMV];
__device__ __half g_cWoT[(size_t)DIMV * INNERV];
__device__ __half g_cWin[(size_t)2 * FFH * DIMV];
__device__ __half g_cWoutP[(size_t)DIMV * LDT];

// ---------------- helpers ---------------------------------------------------------
__device__ __forceinline__ void mma_f16(float d[4], const uint32_t a[4], const uint32_t b[2]) {
    asm volatile(
        "mma.sync.aligned.m16n8k16.row.col.f32.f16.f16.f32 "
        "{%0,%1,%2,%3},{%4,%5,%6,%7},{%8,%9},{%0,%1,%2,%3};\n"
        : "+f"(d[0]), "+f"(d[1]), "+f"(d[2]), "+f"(d[3])
        : "r"(a[0]), "r"(a[1]), "r"(a[2]), "r"(a[3]), "r"(b[0]), "r"(b[1]));
}
__device__ __forceinline__ void ldsm4(uint32_t r[4], uint32_t saddr) {
    asm volatile("ldmatrix.sync.aligned.m8n8.x4.shared.b16 {%0,%1,%2,%3}, [%4];"
        : "=r"(r[0]), "=r"(r[1]), "=r"(r[2]), "=r"(r[3]) : "r"(saddr));
}
__device__ __forceinline__ void ldsm4t(uint32_t r[4], uint32_t saddr) {
    asm volatile("ldmatrix.sync.aligned.m8n8.x4.trans.shared.b16 {%0,%1,%2,%3}, [%4];"
        : "=r"(r[0]), "=r"(r[1]), "=r"(r[2]), "=r"(r[3]) : "r"(saddr));
}
__device__ __forceinline__ void cp16(uint32_t s, const void* g) {
    asm volatile("cp.async.cg.shared.global [%0], [%1], 16;\n" :: "r"(s), "l"(g));
}
__device__ __forceinline__ void cp_commit() { asm volatile("cp.async.commit_group;\n"); }
__device__ __forceinline__ void cp_wait0()  { asm volatile("cp.async.wait_group 0;\n"); }
__device__ __forceinline__ float qmax2(float v) {
    v = fmaxf(v, __shfl_xor_sync(0xffffffffu, v, 1));
    v = fmaxf(v, __shfl_xor_sync(0xffffffffu, v, 2));
    return v;
}
__device__ __forceinline__ float qsum2(float v) {
    v += __shfl_xor_sync(0xffffffffu, v, 1);
    v += __shfl_xor_sync(0xffffffffu, v, 2);
    return v;
}

// ---------------- weight preconvert kernels ---------------------------------------
__global__ void cvtT_kernel(const float* __restrict__ in, __half* __restrict__ out,
                            int K, int N) {
    __shared__ float tile[32][33];
    int n0 = blockIdx.x * 32, k0 = blockIdx.y * 32;
    int tx = threadIdx.x, ty0 = threadIdx.y;
    #pragma unroll
    for (int ty = ty0; ty < 32; ty += 8)
        tile[ty][tx] = in[(size_t)(k0 + ty) * N + n0 + tx];
    __syncthreads();
    #pragma unroll
    for (int ty = ty0; ty < 32; ty += 8)
        out[(size_t)(n0 + ty) * K + k0 + tx] = __float2half(tile[tx][ty]);
}
__global__ void cvtH_kernel(const float4* __restrict__ in, __half2* __restrict__ out, int n4) {
    int i = blockIdx.x * blockDim.x + threadIdx.x;
    int stride = gridDim.x * blockDim.x;
    for (; i < n4; i += stride) {
        float4 v = in[i];
        out[2 * i]     = __floats2half2_rn(v.x, v.y);
        out[2 * i + 1] = __floats2half2_rn(v.z, v.w);
    }
}
__global__ void cvt_pad_kernel(const float* __restrict__ in, __half* __restrict__ out) {
    int r = blockIdx.y;
    int c = blockIdx.x * 256 + threadIdx.x;
    if (c < LDT) out[(size_t)r * LDT + c] =
        (c < FFH) ? __float2half(in[(size_t)r * FFH + c]) : __half(0.f);
}

// ---------------- CPB: 8 rel-positions per block ----------------------------------
#define CPB_R 8
__global__ void cpb_kernel(const float* __restrict__ w1, const float* __restrict__ b1,
                           const float* __restrict__ w2, const float* __restrict__ b2,
                           const float* __restrict__ w3, const float* __restrict__ b3,
                           float* __restrict__ table) {
    __shared__ float h1[CPB_R][CPBD];
    __shared__ float h2[CPB_R][CPBD];
    int t = threadIdx.x;
    int r0 = blockIdx.x * CPB_R;
    #pragma unroll
    for (int r = 0; r < CPB_R; r++) {
        int ridx = r0 + r;
        float rf = (float)(ridx - 511);
        float sgn = (rf > 0.f) ? 1.f : ((rf < 0.f) ? -1.f : 0.f);
        float rel = sgn * logf(fabsf(rf) + 1.f);
        float z = rel * w1[t] + b1[t];
        h1[r][t] = z / (1.f + expf(-z));
    }
    __syncthreads();
    float acc[CPB_R];
    #pragma unroll
    for (int r = 0; r < CPB_R; r++) acc[r] = b2[t];
    for (int j = 0; j < CPBD; j++) {
        float wv = w2[j * CPBD + t];
        #pragma unroll
        for (int r = 0; r < CPB_R; r++) acc[r] += h1[r][j] * wv;
    }
    #pragma unroll
    for (int r = 0; r < CPB_R; r++) {
        float z = acc[r];
        h2[r][t] = z / (1.f + expf(-z));
    }
    __syncthreads();
    int w = t >> 5, lane = t & 31;
    #pragma unroll
    for (int r = 0; r < CPB_R; r++) {
        float a2 = 0.f;
        #pragma unroll 4
        for (int i = lane; i < CPBD; i += 32) a2 += h2[r][i] * w3[i * HEADS + w];
        #pragma unroll
        for (int off = 16; off; off >>= 1) a2 += __shfl_down_sync(0xffffffffu, a2, off);
        int ridx = r0 + r;
        if (lane == 0 && ridx < 1023) table[w * 1023 + ridx] = a2 + b3[w];
    }
}

// ---------------- sequence-axis LayerNorm (float4 loads, half out) ----------------
__global__ void seqln_kernel(const float* __restrict__ x, const float* __restrict__ g,
                             __half* __restrict__ xn) {
    int d4 = blockIdx.x * blockDim.x + threadIdx.x;   // 0..255 (float4 index)
    int b = blockIdx.y;
    const float4* xb = (const float4*)(x + (size_t)b * SEQ * DIMV);
    float4 s = make_float4(0.f, 0.f, 0.f, 0.f), ss = make_float4(0.f, 0.f, 0.f, 0.f);
    for (int n = 0; n < SEQ; n++) {
        float4 v = xb[n * (DIMV / 4) + d4];
        s.x += v.x; s.y += v.y; s.z += v.z; s.w += v.w;
        ss.x += v.x * v.x; ss.y += v.y * v.y; ss.z += v.z * v.z; ss.w += v.w * v.w;
    }
    float4 gv = ((const float4*)g)[d4];
    float mean[4], inv[4];
    float sa[4] = {s.x, s.y, s.z, s.w}, qa[4] = {ss.x, ss.y, ss.z, ss.w};
    float ga[4] = {gv.x, gv.y, gv.z, gv.w};
    #pragma unroll
    for (int e = 0; e < 4; e++) {
        mean[e] = sa[e] * (1.f / SEQ);
        float var = qa[e] * (1.f / SEQ) - mean[e] * mean[e];
        inv[e] = rsqrtf(fmaxf(var, EPSV)) * ga[e];
    }
    __half* ob = xn + (size_t)b * SEQ * DIMV + d4 * 4;
    for (int n = 0; n < SEQ; n++) {
        float4 v = xb[n * (DIMV / 4) + d4];
        __half2 h0 = __floats2half2_rn((v.x - mean[0]) * inv[0], (v.y - mean[1]) * inv[1]);
        __half2 h1 = __floats2half2_rn((v.z - mean[2]) * inv[2], (v.w - mean[3]) * inv[3]);
        uint2 pk = make_uint2(*(uint32_t*)&h0, *(uint32_t*)&h1);
        *(uint2*)&ob[(size_t)n * DIMV] = pk;
    }
}

// ---------------- fused flash attention (single-barrier pipeline) -----------------
#define FA_ST  72
#define FA_QS  0
#define FA_KS  (FA_QS + 128*FA_ST)
#define FA_VS  (FA_KS + 2*64*FA_ST)
#define FA_PS  (FA_VS + 2*64*FA_ST)
#define FA_HEND (FA_PS + 8*16*FA_ST)
#define FA_BYTES (FA_HEND*2 + 1024*4)

__global__ __launch_bounds__(256, 2)
void flash_kernel(const __half* __restrict__ q, const __half* __restrict__ k,
                  const __half* __restrict__ v, const float* __restrict__ table,
                  __half* __restrict__ o) {
    extern __shared__ char smraw[];
    __half* smh = (__half*)smraw;
    float*  Bi  = (float*)(smraw + FA_HEND * 2);

    const int qt = blockIdx.x;
    const int z  = blockIdx.y;
    const int h  = z & (HEADS - 1);
    const int b  = z >> 4;
    const int qbase = qt * 128;
    const int tid = threadIdx.x;
    const int w = tid >> 5, lane = tid & 31;
    const int gid = lane >> 2, tg = lane & 3;

    const __half* qz = q + (size_t)z * SEQ * DHEAD;
    const __half* kz = k + (size_t)z * SEQ * DHEAD;
    const __half* vz = v + (size_t)z * SEQ * DHEAD;

    const uint32_t sbase = (uint32_t)__cvta_generic_to_shared(smh);

    const int aRowOff = ((lane & 15) * FA_ST) + (lane >> 4) * 8;
    const int kRowOff = (((lane & 7) + ((lane >> 4) & 1) * 8) * FA_ST) + ((lane >> 3) & 1) * 8;
    const int vRowOff = (((lane & 7) + ((lane >> 3) & 1) * 8) * FA_ST) + ((lane >> 4) & 1) * 8;

    #pragma unroll
    for (int c = tid; c < 128 * 8; c += 256) {
        int m = c >> 3, kc = c & 7;
        cp16(sbase + (uint32_t)((FA_QS + m * FA_ST + kc * 8) * 2),
             qz + (qbase + m) * DHEAD + kc * 8);
    }
    for (int i = tid; i < 1023; i += 256) Bi[i] = table[h * 1023 + i];

    auto stage_kv = [&](int buf, int jt) {
        int kb = jt * 64;
        #pragma unroll
        for (int c = tid; c < 64 * 8; c += 256) {
            int r = c >> 3, kc = c & 7;
            cp16(sbase + (uint32_t)((FA_KS + buf * 64 * FA_ST + r * FA_ST + kc * 8) * 2),
                 kz + (kb + r) * DHEAD + kc * 8);
            cp16(sbase + (uint32_t)((FA_VS + buf * 64 * FA_ST + r * FA_ST + kc * 8) * 2),
                 vz + (kb + r) * DHEAD + kc * 8);
        }
    };

    stage_kv(0, 0);
    cp_commit();

    float m_row[2] = {-1e30f, -1e30f};
    float l_row[2] = {0.f, 0.f};
    float oacc[8][4];
    #pragma unroll
    for (int j = 0; j < 8; j++)
        #pragma unroll
        for (int e = 0; e < 4; e++) oacc[j][e] = 0.f;

    __half* Ps = smh + FA_PS + w * 16 * FA_ST;
    const uint32_t qA = sbase + (uint32_t)((FA_QS + w * 16 * FA_ST + aRowOff) * 2);
    const uint32_t pA = sbase + (uint32_t)((FA_PS + w * 16 * FA_ST + aRowOff) * 2);

    int buf = 0;
    for (int jt = 0; jt < 8; jt++) {
        cp_wait0();
        __syncthreads();                 // buf(jt) visible; prior reads of buf^1 retired
        if (jt + 1 < 8) { stage_kv(buf ^ 1, jt + 1); cp_commit(); }

        const uint32_t kB = sbase + (uint32_t)((FA_KS + buf * 64 * FA_ST + kRowOff) * 2);
        const uint32_t vB = sbase + (uint32_t)((FA_VS + buf * 64 * FA_ST + vRowOff) * 2);
        const int kb = jt * 64;

        float s[8][4];
        #pragma unroll
        for (int j = 0; j < 8; j++)
            #pragma unroll
            for (int e = 0; e < 4; e++) s[j][e] = 0.f;
        #pragma unroll
        for (int ks = 0; ks < 64; ks += 16) {
            uint32_t a[4];
            ldsm4(a, qA + (uint32_t)(ks * 2));
            #pragma unroll
            for (int jj = 0; jj < 4; jj++) {
                uint32_t bk[4];
                ldsm4(bk, kB + (uint32_t)((jj * 16 * FA_ST + ks) * 2));
                mma_f16(s[2 * jj],     a, &bk[0]);
                mma_f16(s[2 * jj + 1], a, &bk[2]);
            }
        }

        int qi0 = qbase + w * 16 + gid;
        float mx0 = -1e30f, mx1 = -1e30f;
        #pragma unroll
        for (int j = 0; j < 8; j++) {
            int kj = kb + j * 8 + 2 * tg;
            s[j][0] = s[j][0] * 0.125f + Bi[qi0 - kj + 511];
            s[j][1] = s[j][1] * 0.125f + Bi[qi0 - kj + 510];
            s[j][2] = s[j][2] * 0.125f + Bi[qi0 + 8 - kj + 511];
            s[j][3] = s[j][3] * 0.125f + Bi[qi0 + 8 - kj + 510];
            mx0 = fmaxf(mx0, fmaxf(s[j][0], s[j][1]));
            mx1 = fmaxf(mx1, fmaxf(s[j][2], s[j][3]));
        }
        mx0 = qmax2(mx0); mx1 = qmax2(mx1);
        float mn0 = fmaxf(m_row[0], mx0), mn1 = fmaxf(m_row[1], mx1);
        float sc0 = __expf(m_row[0] - mn0), sc1 = __expf(m_row[1] - mn1);
        float rs0 = 0.f, rs1 = 0.f;
        #pragma unroll
        for (int j = 0; j < 8; j++) {
            s[j][0] = __expf(s[j][0] - mn0);
            s[j][1] = __expf(s[j][1] - mn0);
            s[j][2] = __expf(s[j][2] - mn1);
            s[j][3] = __expf(s[j][3] - mn1);
            rs0 += s[j][0] + s[j][1];
            rs1 += s[j][2] + s[j][3];
        }
        rs0 = qsum2(rs0); rs1 = qsum2(rs1);
        l_row[0] = l_row[0] * sc0 + rs0;
        l_row[1] = l_row[1] * sc1 + rs1;
        m_row[0] = mn0; m_row[1] = mn1;
        #pragma unroll
        for (int j = 0; j < 8; j++) {
            oacc[j][0] *= sc0; oacc[j][1] *= sc0;
            oacc[j][2] *= sc1; oacc[j][3] *= sc1;
        }

        #pragma unroll
        for (int j = 0; j < 8; j++) {
            *(__half2*)&Ps[gid * FA_ST + j * 8 + 2 * tg]       = __floats2half2_rn(s[j][0], s[j][1]);
            *(__half2*)&Ps[(gid + 8) * FA_ST + j * 8 + 2 * tg] = __floats2half2_rn(s[j][2], s[j][3]);
        }
        __syncwarp();

        #pragma unroll
        for (int ks = 0; ks < 64; ks += 16) {
            uint32_t a[4];
            ldsm4(a, pA + (uint32_t)(ks * 2));
            #pragma unroll
            for (int jj = 0; jj < 4; jj++) {
                uint32_t bv[4];
                ldsm4t(bv, vB + (uint32_t)((ks * FA_ST + jj * 16) * 2));
                mma_f16(oacc[2 * jj],     a, &bv[0]);
                mma_f16(oacc[2 * jj + 1], a, &bv[2]);
            }
        }
        __syncwarp();
        buf ^= 1;
    }

    float inv0 = 1.f / l_row[0], inv1 = 1.f / l_row[1];
    int qi = qbase + w * 16 + gid;
    #pragma unroll
    for (int j = 0; j < 8; j++) {
        int d = j * 8 + 2 * tg;
        size_t r0 = ((size_t)(b * SEQ + qi) * INNERV) + h * DHEAD + d;
        size_t r1 = ((size_t)(b * SEQ + qi + 8) * INNERV) + h * DHEAD + d;
        *(__half2*)&o[r0] = __floats2half2_rn(oacc[j][0] * inv0, oacc[j][1] * inv0);
        *(__half2*)&o[r1] = __floats2half2_rn(oacc[j][2] * inv1, oacc[j][3] * inv1);
    }
}

// ---------------- channel LayerNorm (uint4 stat loads, half2 writes) --------------
// t padding cols [FFH,LDT) are zero (zero-init, never written) => stats unaffected;
// cWoutP padding is zero => padding values of t are irrelevant to FFO.
__global__ void chanln_kernel(__half* __restrict__ tb, const float* __restrict__ gg) {
    int m = blockIdx.x;
    __half* row = tb + (size_t)m * LDT;
    int t = threadIdx.x;
    float s = 0.f, ss = 0.f;
    const uint4* r4 = (const uint4*)row;
    for (int j = t; j < LDT / 8; j += 256) {          // 344 uint4 (padding zeros harmless)
        uint4 pk = r4[j];
        const __half2* h2p = (const __half2*)&pk;
        #pragma unroll
        for (int e = 0; e < 4; e++) {
            float2 f = __half22float2(h2p[e]);
            s += f.x + f.y;
            ss += f.x * f.x + f.y * f.y;
        }
    }
    __shared__ float r1[256], r2[256];
    r1[t] = s; r2[t] = ss; __syncthreads();
    for (int k = 128; k; k >>= 1) { if (t < k) { r1[t] += r1[t + k]; r2[t] += r2[t + k]; } __syncthreads(); }
    float mean = r1[0] * (1.f / FFH);
    float var  = r2[0] * (1.f / FFH) - mean * mean;
    float inv  = rsqrtf(fmaxf(var, EPSV));
    for (int j2 = t; j2 < FFH / 2; j2 += 256) {       // 1365 half2 (FFH even)
        float2 f = __half22float2(*(__half2*)&row[2 * j2]);
        float a = (f.x - mean) * inv * gg[2 * j2];
        float b = (f.y - mean) * inv * gg[2 * j2 + 1];
        *(__half2*)&row[2 * j2] = __floats2half2_rn(a, b);
    }
}

// ---------------- fp16 tensor-core GEMM, single-barrier BK=64 dbl-buf, 2 CTA/SM ---
// EPI: 1 = Cf = v + R (float); 2 = merged-qkv head-split half store;
//      4 = y float + yh half
template<int BM, int BN, int BK, int WM, int WN, int EPI>
__global__ __launch_bounds__(256, 2)
void hgemm(const __half* __restrict__ A, const __half* __restrict__ B,
           float* __restrict__ Cf, __half* __restrict__ Ch, const float* __restrict__ R,
           int M, int Nn, int K, int lda, int ldb, int ldc) {
    constexpr int WARPS_N = BN / WN;
    constexpr int MT = WM / 16, NT = WN / 8;
    constexpr int AST = BK + 8;
    constexpr int BST = BK + 8;
    constexpr int ABUF = BM * AST;
    constexpr int BBUF = BN * BST;

    extern __shared__ char smraw[];
    __half* Asm = (__half*)smraw;
    __half* Bsm = Asm + 2 * ABUF;

    const int m0 = blockIdx.y * BM;
    const int n0 = blockIdx.x * BN;
    const int tid = threadIdx.x;
    const int warp = tid >> 5, lane = tid & 31;
    const int wr = warp / WARPS_N, wc = warp % WARPS_N;
    const int gid = lane >> 2, tg = lane & 3;

    const uint32_t sAb = (uint32_t)__cvta_generic_to_shared(Asm);
    const uint32_t sBb = (uint32_t)__cvta_generic_to_shared(Bsm);

    const int aRow  = wr * WM + (lane & 15);
    const int aKoff = (lane & 16) >> 1;
    const int bRow  = wc * WN + ((lane >> 4) & 1) * 8 + (lane & 7);
    const int bKoff = ((lane >> 3) & 1) * 8;

    float acc[MT][NT][4];
    #pragma unroll
    for (int i = 0; i < MT; i++)
        #pragma unroll
        for (int j = 0; j < NT; j++)
            #pragma unroll
            for (int e = 0; e < 4; e++) acc[i][j][e] = 0.f;

    const int NIT = K / BK;

    auto stage = [&](int b, int k0) {
        constexpr int ACH = BK / 8;
        #pragma unroll
        for (int c = tid; c < BM * ACH; c += 256) {
            int m = c / ACH, kc = c % ACH;
            cp16(sAb + (uint32_t)((b * ABUF + m * AST + kc * 8) * 2),
                 A + (size_t)(m0 + m) * lda + k0 + kc * 8);
        }
        constexpr int BCH = BK / 8;
        #pragma unroll
        for (int c = tid; c < BN * BCH; c += 256) {
            int n = c / BCH, kc = c % BCH;
            cp16(sBb + (uint32_t)((b * BBUF + n * BST + kc * 8) * 2),
                 B + (size_t)(n0 + n) * ldb + k0 + kc * 8);
        }
    };

    stage(0, 0);
    cp_commit();
    int buf = 0;
    for (int it = 0; it < NIT; it++) {
        cp_wait0();
        __syncthreads();                 // buf(it) visible; prior reads of buf^1 retired
        if (it + 1 < NIT) { stage(buf ^ 1, (it + 1) * BK); cp_commit(); }

        const uint32_t aB = sAb + (uint32_t)((buf * ABUF + aRow * AST + aKoff) * 2);
        const uint32_t bB = sBb + (uint32_t)((buf * BBUF + bRow * BST + bKoff) * 2);
        #pragma unroll
        for (int ks = 0; ks < BK; ks += 16) {
            uint32_t af[MT][4];
            uint32_t bf[NT / 2][4];
            #pragma unroll
            for (int i = 0; i < MT; i++)
                ldsm4(af[i], aB + (uint32_t)((i * 16 * AST + ks) * 2));
            #pragma unroll
            for (int jj = 0; jj < NT / 2; jj++)
                ldsm4(bf[jj], bB + (uint32_t)((jj * 16 * BST + ks) * 2));
            #pragma unroll
            for (int i = 0; i < MT; i++)
                #pragma unroll
                for (int jj = 0; jj < NT / 2; jj++) {
                    mma_f16(acc[i][2 * jj],     af[i], &bf[jj][0]);
                    mma_f16(acc[i][2 * jj + 1], af[i], &bf[jj][2]);
                }
        }
        buf ^= 1;
    }

    #pragma unroll
    for (int i = 0; i < MT; i++) {
        #pragma unroll
        for (int j = 0; j < NT; j++) {
            int m_lo = m0 + wr * WM + i * 16 + gid;
            int n_e  = n0 + wc * WN + j * 8 + 2 * tg;
            if (EPI == 2) {
                #pragma unroll
                for (int half_i = 0; half_i < 2; half_i++) {
                    int m = m_lo + half_i * 8;
                    if (m < M && n_e + 1 < Nn) {
                        int which = n_e >> 10;
                        int nn2 = n_e & 1023;
                        int hh = nn2 >> 6, d = nn2 & (DHEAD - 1);
                        int bb = m >> 9, sq = m & (SEQ - 1);
                        __half2 hv = __floats2half2_rn(acc[i][j][2 * half_i], acc[i][j][2 * half_i + 1]);
                        *(__half2*)&Ch[(size_t)which * MROWS * INNERV +
                                       ((((size_t)bb * HEADS + hh) * SEQ + sq) << 6) + d] = hv;
                    }
                }
            } else {
                #pragma unroll
                for (int e = 0; e < 4; e++) {
                    int m = m_lo + ((e >= 2) ? 8 : 0);
                    int n = n_e + (e & 1);
                    if (m < M && n < Nn) {
                        float v = acc[i][j][e];
                        if (EPI == 1) {
                            Cf[(size_t)m * ldc + n] = v + R[(size_t)m * ldc + n];
                        } else { // EPI == 4
                            float r = v + R[(size_t)m * ldc + n];
                            Cf[(size_t)m * ldc + n] = r;
                            Ch[(size_t)m * ldc + n] = __float2half(r);
                        }
                    }
                }
            }
        }
    }
}

// ---------------- fp16 GEGLU GEMM, single-barrier BK=64 dbl-buf, 2 CTA/SM ---------
template<int BM, int BN, int BK, int WM, int WN>
__global__ __launch_bounds__(256, 2)
void hgemm_geglu(const __half* __restrict__ A, const __half* __restrict__ B,
                 __half* __restrict__ C, int M, int Nn, int K, int ldb, int ldc) {
    constexpr int WARPS_N = BN / WN;
    constexpr int MT = WM / 16, NT = WN / 8;
    constexpr int AST = BK + 8;
    constexpr int BST = BK + 8;
    constexpr int ABUF = BM * AST;
    constexpr int BBUF = BN * BST;

    extern __shared__ char smraw[];
    __half* Asm = (__half*)smraw;
    __half* B1m = Asm + 2 * ABUF;
    __half* B2m = B1m + 2 * BBUF;

    const int m0 = blockIdx.y * BM;
    const int n0 = blockIdx.x * BN;
    const int tid = threadIdx.x;
    const int warp = tid >> 5, lane = tid & 31;
    const int wr = warp / WARPS_N, wc = warp % WARPS_N;
    const int gid = lane >> 2, tg = lane & 3;

    const uint32_t sAb = (uint32_t)__cvta_generic_to_shared(Asm);
    const uint32_t sB1 = (uint32_t)__cvta_generic_to_shared(B1m);
    const uint32_t sB2 = (uint32_t)__cvta_generic_to_shared(B2m);

    const int aRow  = wr * WM + (lane & 15);
    const int aKoff = (lane & 16) >> 1;
    const int bRow  = wc * WN + ((lane >> 4) & 1) * 8 + (lane & 7);
    const int bKoff = ((lane >> 3) & 1) * 8;

    float a1[MT][NT][4], a2[MT][NT][4];
    #pragma unroll
    for (int i = 0; i < MT; i++)
        #pragma unroll
        for (int j = 0; j < NT; j++)
            #pragma unroll
            for (int e = 0; e < 4; e++) { a1[i][j][e] = 0.f; a2[i][j][e] = 0.f; }

    const int NIT = K / BK;

    auto stage = [&](int b, int k0) {
        constexpr int ACH = BK / 8;
        #pragma unroll
        for (int c = tid; c < BM * ACH; c += 256) {
            int m = c / ACH, kc = c % ACH;
            cp16(sAb + (uint32_t)((b * ABUF + m * AST + kc * 8) * 2),
                 A + (size_t)(m0 + m) * K + k0 + kc * 8);
        }
        constexpr int BCH = BK / 8;
        #pragma unroll
        for (int c = tid; c < BN * BCH; c += 256) {
            int n = c / BCH, kc = c % BCH;
            int gn = n0 + n; if (gn > FFH - 1) gn = FFH - 1;
            uint32_t off = (uint32_t)((b * BBUF + n * BST + kc * 8) * 2);
            cp16(sB1 + off, B + (size_t)gn * ldb + k0 + kc * 8);
            cp16(sB2 + off, B + (size_t)(gn + FFH) * ldb + k0 + kc * 8);
        }
    };

    stage(0, 0);
    cp_commit();
    int buf = 0;
    for (int it = 0; it < NIT; it++) {
        cp_wait0();
        __syncthreads();
        if (it + 1 < NIT) { stage(buf ^ 1, (it + 1) * BK); cp_commit(); }

        const uint32_t aB  = sAb + (uint32_t)((buf * ABUF + aRow * AST + aKoff) * 2);
        const uint32_t bB1 = sB1 + (uint32_t)((buf * BBUF + bRow * BST + bKoff) * 2);
        const uint32_t bB2 = sB2 + (uint32_t)((buf * BBUF + bRow * BST + bKoff) * 2);
        #pragma unroll
        for (int ks = 0; ks < BK; ks += 16) {
            uint32_t af[MT][4];
            uint32_t bf1[NT / 2][4], bf2[NT / 2][4];
            #pragma unroll
            for (int i = 0; i < MT; i++)
                ldsm4(af[i], aB + (uint32_t)((i * 16 * AST + ks) * 2));
            #pragma unroll
            for (int jj = 0; jj < NT / 2; jj++) {
                ldsm4(bf1[jj], bB1 + (uint32_t)((jj * 16 * BST + ks) * 2));
                ldsm4(bf2[jj], bB2 + (uint32_t)((jj * 16 * BST + ks) * 2));
            }
            #pragma unroll
            for (int i = 0; i < MT; i++)
                #pragma unroll
                for (int jj = 0; jj < NT / 2; jj++) {
                    mma_f16(a1[i][2 * jj],     af[i], &bf1[jj][0]);
                    mma_f16(a1[i][2 * jj + 1], af[i], &bf1[jj][2]);
                    mma_f16(a2[i][2 * jj],     af[i], &bf2[jj][0]);
                    mma_f16(a2[i][2 * jj + 1], af[i], &bf2[jj][2]);
                }
        }
        buf ^= 1;
    }

    #pragma unroll
    for (int i = 0; i < MT; i++) {
        #pragma unroll
        for (int j = 0; j < NT; j++) {
            #pragma unroll
            for (int e = 0; e < 4; e++) {
                int m = m0 + wr * WM + i * 16 + gid + ((e >= 2) ? 8 : 0);
                int n = n0 + wc * WN + j * 8 + 2 * tg + (e & 1);
                if (m < M && n < Nn) {
                    float g  = a2[i][j][e];
                    float ge = 0.5f * g * (1.f + erff(g * 0.70710678118654752f));
                    C[(size_t)m * ldc + n] = __float2half(a1[i][j][e] * ge);
                }
            }
        }
    }
}

// ---------------- launch ---------------------------------------------------------
extern "C" void kernel_launch(void* const* d_in, const int* in_sizes, int n_in,
                              void* d_out, int out_size) {
    const float* x      = (const float*)d_in[0];
    const float* g_ln   = (const float*)d_in[1];
    const float* Wq     = (const float*)d_in[2];
    const float* Wkv    = (const float*)d_in[3];
    const float* Wo     = (const float*)d_in[4];
    const float* cpb_w1 = (const float*)d_in[5];
    const float* cpb_b1 = (const float*)d_in[6];
    const float* cpb_w2 = (const float*)d_in[7];
    const float* cpb_b2 = (const float*)d_in[8];
    const float* cpb_w3 = (const float*)d_in[9];
    const float* cpb_b3 = (const float*)d_in[10];
    const float* ff_w_in  = (const float*)d_in[11];
    const float* ff_g     = (const float*)d_in[12];
    const float* ff_w_out = (const float*)d_in[13];
    float* out = (float*)d_out;

    float *bias, *y;
    __half *xn, *qkv, *o, *yh, *t;
    __half *cWqkvT, *cWoT, *cWin, *cWoutP;
    cudaGetSymbolAddress((void**)&bias, g_bias);
    cudaGetSymbolAddress((void**)&xn,  g_xn);
    cudaGetSymbolAddress((void**)&qkv, g_qkv);
    cudaGetSymbolAddress((void**)&o,   g_o);
    cudaGetSymbolAddress((void**)&y,   g_y);
    cudaGetSymbolAddress((void**)&yh,  g_yh);
    cudaGetSymbolAddress((void**)&t,   g_t);
    cudaGetSymbolAddress((void**)&cWqkvT, g_cWqkvT);
    cudaGetSymbolAddress((void**)&cWoT,   g_cWoT);
    cudaGetSymbolAddress((void**)&cWin,   g_cWin);
    cudaGetSymbolAddress((void**)&cWoutP, g_cWoutP);

    auto T_QKV = hgemm<128,128,64,64,32,2>;
    auto T_OP  = hgemm<128,128,64,64,32,4>;
    auto T_FFO = hgemm<128,128,64,64,32,1>;
    auto T_GG  = hgemm_geglu<128,64,64,64,16>;

    const int SM_G  = (2*128*72 + 2*128*72) * 2;     // 73728 B (2 CTAs/SM)
    const int SM_GG = (2*128*72 + 4*64*72)  * 2;     // 73728 B

    cudaFuncSetAttribute(T_QKV, cudaFuncAttributeMaxDynamicSharedMemorySize, SM_G);
    cudaFuncSetAttribute(T_OP,  cudaFuncAttributeMaxDynamicSharedMemorySize, SM_G);
    cudaFuncSetAttribute(T_FFO, cudaFuncAttributeMaxDynamicSharedMemorySize, SM_G);
    cudaFuncSetAttribute(T_GG,  cudaFuncAttributeMaxDynamicSharedMemorySize, SM_GG);
    cudaFuncSetAttribute(flash_kernel, cudaFuncAttributeMaxDynamicSharedMemorySize, FA_BYTES);

    // 0) weight preconversion
    cvtT_kernel<<<dim3(32,32), dim3(32,8)>>>(Wq,  cWqkvT,                       DIMV, INNERV);
    cvtT_kernel<<<dim3(64,32), dim3(32,8)>>>(Wkv, cWqkvT + (size_t)INNERV*DIMV, DIMV, 2*INNERV);
    cvtT_kernel<<<dim3(32,32), dim3(32,8)>>>(Wo,  cWoT,  INNERV, DIMV);
    cvtH_kernel<<<512, 256>>>((const float4*)ff_w_in, (__half2*)cWin, 2*FFH*DIMV/4);
    cvt_pad_kernel<<<dim3((LDT+255)/256, DIMV), 256>>>(ff_w_out, cWoutP);

    // 1) CPB bias table (8 rel-positions per block)
    cpb_kernel<<<128, 512>>>(cpb_w1, cpb_b1, cpb_w2, cpb_b2, cpb_w3, cpb_b3, bias);

    // 2) sequence-axis LayerNorm (vectorized, half out)
    seqln_kernel<<<dim3(1, BATCH), 256>>>(x, g_ln, xn);

    // 3) merged Q/K/V projection (N=3072)
    T_QKV<<<dim3(24,64),256,SM_G>>>(xn, cWqkvT, nullptr, qkv, nullptr,
        MROWS, 3*INNERV, DIMV, DIMV, DIMV, 0);

    // 4-6) fused flash attention (2 CTAs/SM)
    flash_kernel<<<dim3(SEQ/128, BATCH*HEADS), 256, FA_BYTES>>>(
        qkv, qkv + (size_t)MROWS*INNERV, qkv + (size_t)2*MROWS*INNERV, bias, o);

    // 7) y = O @ Wo + x  (float y + half mirror)
    T_OP<<<dim3(8,64),256,SM_G>>>(o, cWoT, y, yh, x,
        MROWS, DIMV, INNERV, INNERV, INNERV, DIMV);

    // 8) FF-in + fused GEGLU (half out)
    T_GG<<<dim3((FFH+63)/64, 64),256,SM_GG>>>(yh, cWin, t,
        MROWS, FFH, DIMV, DIMV, LDT);

    // 9) channel LayerNorm (vectorized; padding untouched, stays zero)
    chanln_kernel<<<MROWS, 256>>>(t, ff_g);

    // 10) out = t @ cWoutP^T + y  (fp32 residual add)
    T_FFO<<<dim3(8,64),256,SM_G>>>(t, cWoutP, out, nullptr, y,
        MROWS, DIMV, LDT, LDT, LDT, DIMV);
}